// round 14
// baseline (speedup 1.0000x reference)
#include <cuda_runtime.h>
#include <cuda_fp16.h>
#include <math.h>
#include <stdint.h>

#define NT   2048
#define DIM  2048
#define HID  1408
#define NE   16
#define TOPK 4
#define KC   32
#define G_W  (2 * HID)     // G row width: [W1 outputs | W3 outputs]

typedef __half fp16;

// ---- routing scratch ----
__device__ int   g_counts[NE];
__device__ int   g_entries[NE * NT];
__device__ float g_slotw[NT * TOPK];

// ---- staging ----
__device__ fp16  g_x16[NT * DIM];
__device__ fp16  g_Gs[(size_t)NT * G_W];             // shared raw up outputs
__device__ fp16  g_Gr[(size_t)NT * TOPK * G_W];      // routed raw up outputs (slot-major)
__device__ fp16  g_Hs[(size_t)NT * HID];
__device__ fp16  g_Hr[(size_t)NT * TOPK * HID];
__device__ float g_Yr[(size_t)NT * TOPK * DIM];

__global__ void zero_counts_kernel() {
    if (threadIdx.x < NE) g_counts[threadIdx.x] = 0;
}

__device__ __forceinline__ uint32_t h2u(float a, float b) {
    __half2 h = __floats2half2_rn(a, b);
    return *(uint32_t*)&h;
}

// ---- fp32 -> fp16 convert (x) ----
__global__ __launch_bounds__(256) void cvtx_kernel(const float4* __restrict__ src,
                                                   uint2* __restrict__ dst)
{
    int stride = gridDim.x * blockDim.x;
    int i = blockIdx.x * blockDim.x + threadIdx.x;
    float4 v[8];
    #pragma unroll
    for (int j = 0; j < 8; j++) v[j] = __ldcs(src + i + j * stride);
    #pragma unroll
    for (int j = 0; j < 8; j++) {
        uint2 o;
        o.x = h2u(v[j].x, v[j].y);
        o.y = h2u(v[j].z, v[j].w);
        __stcs(dst + i + j * stride, o);
    }
}

// ---------------- gate ----------------
__global__ __launch_bounds__(256) void gate_kernel(const float* __restrict__ x,
                                                   const float* __restrict__ gw,
                                                   const float* __restrict__ gb)
{
    int t = blockIdx.x;
    __shared__ float xs[DIM];
    for (int i = threadIdx.x; i < DIM; i += blockDim.x)
        xs[i] = x[(size_t)t * DIM + i];
    __syncthreads();

    __shared__ float logits[NE];
    int warp = threadIdx.x >> 5, lane = threadIdx.x & 31;
    for (int e = warp; e < NE; e += 8) {
        const float* w = gw + (size_t)e * DIM;
        float s = 0.f;
        for (int d = lane; d < DIM; d += 32) s += w[d] * xs[d];
        #pragma unroll
        for (int o = 16; o > 0; o >>= 1) s += __shfl_down_sync(0xffffffffu, s, o);
        if (lane == 0) logits[e] = s;
    }
    __syncthreads();

    if (threadIdx.x == 0) {
        float sc[NE];
        #pragma unroll
        for (int e = 0; e < NE; e++)
            sc[e] = 1.f / (1.f + expf(-logits[e])) + gb[e];
        int idx[TOPK]; float wv[TOPK]; float sum = 0.f;
        bool used[NE];
        #pragma unroll
        for (int e = 0; e < NE; e++) used[e] = false;
        #pragma unroll
        for (int k = 0; k < TOPK; k++) {
            float best = -1e30f; int bi = 0;
            #pragma unroll
            for (int e = 0; e < NE; e++)
                if (!used[e] && sc[e] > best) { best = sc[e]; bi = e; }
            used[bi] = true; idx[k] = bi; wv[k] = best; sum += best;
        }
        float inv = 1.f / sum;
        #pragma unroll
        for (int k = 0; k < TOPK; k++) {
            int e = idx[k];
            int pos = atomicAdd(&g_counts[e], 1);
            g_entries[e * NT + pos] = t * TOPK + k;
            g_slotw[t * TOPK + k]   = wv[k] * inv;
        }
    }
}

__device__ __forceinline__ float sigmoidf_(float v) { return 1.f / (1.f + expf(-v)); }

// ---------------- asm helpers ----------------
__device__ __forceinline__ uint32_t saddr(const void* p) {
    return (uint32_t)__cvta_generic_to_shared(p);
}
__device__ __forceinline__ void cpa(uint32_t dst, const void* src) {
    asm volatile("cp.async.cg.shared.global [%0], [%1], 16;" :: "r"(dst), "l"(src));
}
__device__ __forceinline__ void cp_commit() { asm volatile("cp.async.commit_group;"); }
__device__ __forceinline__ void cp_wait2()  { asm volatile("cp.async.wait_group 2;"); }
__device__ __forceinline__ void ldsm_x4(uint32_t r[4], uint32_t a) {
    asm volatile("ldmatrix.sync.aligned.m8n8.x4.shared.b16 {%0,%1,%2,%3}, [%4];"
                 : "=r"(r[0]), "=r"(r[1]), "=r"(r[2]), "=r"(r[3]) : "r"(a));
}
__device__ __forceinline__ void ldsm_x4t(uint32_t r[4], uint32_t a) {
    asm volatile("ldmatrix.sync.aligned.m8n8.x4.trans.shared.b16 {%0,%1,%2,%3}, [%4];"
                 : "=r"(r[0]), "=r"(r[1]), "=r"(r[2]), "=r"(r[3]) : "r"(a));
}
__device__ __forceinline__ void mma16816(float c[4], const uint32_t a[4], const uint32_t b[2]) {
    asm volatile("mma.sync.aligned.m16n8k16.row.col.f32.f16.f16.f32 "
                 "{%0,%1,%2,%3}, {%4,%5,%6,%7}, {%8,%9}, {%0,%1,%2,%3};"
                 : "+f"(c[0]), "+f"(c[1]), "+f"(c[2]), "+f"(c[3])
                 : "r"(a[0]), "r"(a[1]), "r"(a[2]), "r"(a[3]), "r"(b[0]), "r"(b[1]));
}

#define APITCH 40
#define BP     136
#define A_ST   (256 * APITCH)            // 10240 elems
#define B_ST   (32 * BP)                 // 4352 elems
#define STAGE  ((A_ST + B_ST) * 2)       // 29184 B
#define GSMEM  (4 * STAGE)               // 116736 B (1 CTA/SM)

// ======== generic 256x128 GEMM body (shared via macro-ish template) ========
// UP=true : A=x16 (gather by slot->token), B=W1/W3 (ldB=HID), out=G fp16
// UP=false: A=H   (gather by slot),        B=W2    (ldB=DIM), out fp32
template<bool UP>
__global__ __launch_bounds__(512) void gemm_k(
        const fp16* __restrict__ As, const fp16* __restrict__ Ar,
        const float* __restrict__ WAs, const float* __restrict__ WBs,   // UP: W1s,W3s ; DOWN: W2s,(unused)
        const float* __restrict__ WAr, const float* __restrict__ WBr,   // UP: W1r,W3r ; DOWN: W2r,(unused)
        fp16* __restrict__ GOs, fp16* __restrict__ GOr,                 // UP outputs
        float* __restrict__ FOs, float* __restrict__ FOr)               // DOWN outputs
{
    int z = blockIdx.z;
    bool routed = z > 0;
    int e = z - 1;
    int M = routed ? g_counts[e] : NT;
    int m0 = blockIdx.x * 256;
    if (m0 >= M) return;
    int y = blockIdx.y;

    const float* W;
    int n0w;
    int ldB = UP ? HID : DIM;
    if (UP) {
        bool isW3 = y >= (HID / 128);
        int yw = isW3 ? y - HID / 128 : y;
        n0w = yw * 128;
        W = routed ? (isW3 ? WBr + (size_t)e * DIM * HID : WAr + (size_t)e * DIM * HID)
                   : (isW3 ? WBs : WAs);
    } else {
        n0w = y * 128;
        W = routed ? WAr + (size_t)e * HID * DIM : WAs;
    }
    int n0o = y * 128;   // output column base (G columns for UP, DIM for DOWN)

    extern __shared__ char smem[];
    int tid = threadIdx.x, lane = tid & 31, warp = tid >> 5;
    int wm = (warp & 3) * 64, wn = (warp >> 2) * 32;

    // A: one 32-col slab per thread pair (256 rows)
    int ar = tid >> 1, ac = (tid & 1) * 16;
    int gr = m0 + ar; if (gr >= M) gr = m0;
    const fp16* Abase = routed ? Ar : As;
    size_t arow;
    if (UP) arow = routed ? (size_t)(g_entries[e * NT + gr] >> 2) : (size_t)gr;
    else    arow = routed ? (size_t)g_entries[e * NT + gr] : (size_t)gr;
    const fp16* srcA = Abase + arow * (UP ? DIM : HID) + ac;

    // B: 32 rows x 128 cols fp32; 8 floats per thread
    int brow = tid >> 4, bcol = (tid & 15) * 8;
    const float* srcB = W + (size_t)brow * ldB + n0w + bcol;

    uint32_t sb = saddr(smem);
    uint32_t offA = (uint32_t)(ar * APITCH + ac) * 2;
    uint32_t offB = (uint32_t)(A_ST + brow * BP + bcol) * 2;

    float acc[4][4][4] = {};
    float4 bv[2];

    auto loadA = [&](int st, int k0) {
        uint32_t base = sb + st * STAGE;
        cpa(base + offA,      srcA + k0);
        cpa(base + offA + 16, srcA + k0 + 8);
    };
    auto ldgB = [&](int k0) {
        const float4* p = (const float4*)(srcB + (size_t)k0 * ldB);
        bv[0] = __ldg(p); bv[1] = __ldg(p + 1);
    };
    auto stsB = [&](int st) {
        char* base = smem + st * STAGE;
        uint4 o;
        o.x = h2u(bv[0].x, bv[0].y); o.y = h2u(bv[0].z, bv[0].w);
        o.z = h2u(bv[1].x, bv[1].y); o.w = h2u(bv[1].z, bv[1].w);
        *(uint4*)(base + offB) = o;
    };

    // prologue
    ldgB(0);  stsB(0);  ldgB(KC);
    loadA(0, 0);      cp_commit();
    loadA(1, KC);     cp_commit();
    loadA(2, 2 * KC); cp_commit();

    const int KT = (UP ? DIM : HID) / KC;
    for (int t = 0; t < KT; t++) {
        int st = t & 3;
        cp_wait2();
        __syncthreads();
        if (t + 1 < KT) stsB((t + 1) & 3);
        if (t + 2 < KT) ldgB((t + 2) * KC);
        if (t + 3 < KT) loadA((t + 3) & 3, (t + 3) * KC);
        cp_commit();

        uint32_t base = sb + st * STAGE;
        #pragma unroll
        for (int kk = 0; kk < KC; kk += 16) {
            uint32_t a[4][4];
            #pragma unroll
            for (int mi = 0; mi < 4; mi++) {
                uint32_t ao = ((wm + mi * 16 + (lane & 15)) * APITCH + kk + ((lane >> 4) << 3)) * 2;
                ldsm_x4(a[mi], base + ao);
            }
            uint32_t b[2][4];
            #pragma unroll
            for (int g = 0; g < 2; g++) {
                uint32_t bo = ((kk + (lane & 15)) * BP + wn + g * 16 + ((lane >> 4) << 3)) * 2;
                ldsm_x4t(b[g], base + A_ST * 2 + bo);
            }
            #pragma unroll
            for (int ni = 0; ni < 4; ni++) {
                int g = ni >> 1, o = (ni & 1) * 2;
                #pragma unroll
                for (int mi = 0; mi < 4; mi++)
                    mma16816(acc[mi][ni], a[mi], &b[g][o]);
            }
        }
    }

    // epilogue
    #pragma unroll
    for (int mi = 0; mi < 4; mi++)
        #pragma unroll
        for (int half = 0; half < 2; half++) {
            int r = m0 + wm + mi * 16 + (lane >> 2) + half * 8;
            if (r >= M) continue;
            size_t orow;
            if (UP) orow = routed ? (size_t)g_entries[e * NT + r] : (size_t)r;
            else    orow = routed ? (size_t)g_entries[e * NT + r] : (size_t)r;
            if (UP) {
                fp16* G = routed ? GOr : GOs;
                #pragma unroll
                for (int ni = 0; ni < 4; ni++) {
                    __half2 h2 = __floats2half2_rn(acc[mi][ni][half * 2 + 0],
                                                   acc[mi][ni][half * 2 + 1]);
                    *(__half2*)&G[orow * G_W + n0o + wn + ni * 8 + ((lane & 3) << 1)] = h2;
                }
            } else {
                float* out = routed ? FOr : FOs;
                #pragma unroll
                for (int ni = 0; ni < 4; ni++) {
                    float2 o;
                    o.x = acc[mi][ni][half * 2 + 0];
                    o.y = acc[mi][ni][half * 2 + 1];
                    *(float2*)&out[orow * DIM + n0o + wn + ni * 8 + ((lane & 3) << 1)] = o;
                }
            }
        }
}

// ---- act: H = f(G1, G3); ROUTED: silu(g1*g3), shared: silu(g1)*g3 ----
template<bool ROUTED>
__global__ __launch_bounds__(256) void act_kernel(const fp16* __restrict__ G,
                                                  fp16* __restrict__ H, int nitems)
{
    int i = blockIdx.x * blockDim.x + threadIdx.x;
    if (i >= nitems) return;                  // nitems = rows * (HID/8)
    int r = i / (HID / 8);
    int c = (i % (HID / 8)) * 8;
    uint4 u1 = *(const uint4*)&G[(size_t)r * G_W + c];
    uint4 u3 = *(const uint4*)&G[(size_t)r * G_W + HID + c];
    const __half2* p1 = (const __half2*)&u1;
    const __half2* p3 = (const __half2*)&u3;
    uint4 ou;
    __half2* po = (__half2*)&ou;
    #pragma unroll
    for (int j = 0; j < 4; j++) {
        float2 f1 = __half22float2(p1[j]);
        float2 f3 = __half22float2(p3[j]);
        float oa, ob;
        if (ROUTED) {
            float pa = f1.x * f3.x, pb = f1.y * f3.y;
            oa = pa * sigmoidf_(pa);
            ob = pb * sigmoidf_(pb);
        } else {
            oa = f1.x * sigmoidf_(f1.x) * f3.x;
            ob = f1.y * sigmoidf_(f1.y) * f3.y;
        }
        po[j] = __floats2half2_rn(oa, ob);
    }
    *(uint4*)&H[(size_t)r * HID + c] = ou;
}

// ---- gather: out[t] += sum_k w[4t+k] * Yr[4t+k] ----
__global__ __launch_bounds__(256) void gather_kernel(const float* __restrict__ Yr,
                                                     float* __restrict__ out)
{
    int t = blockIdx.x;
    int d0 = threadIdx.x * 8;
    float w[TOPK];
    #pragma unroll
    for (int k = 0; k < TOPK; k++) w[k] = g_slotw[t * TOPK + k];
    size_t obase = (size_t)t * DIM + d0;
    #pragma unroll
    for (int j = 0; j < 2; j++) {
        float4 o = *(const float4*)&out[obase + j * 4];
        #pragma unroll
        for (int k = 0; k < TOPK; k++) {
            float4 yv = __ldcs((const float4*)&Yr[((size_t)t * TOPK + k) * DIM + d0 + j * 4]);
            o.x += w[k] * yv.x; o.y += w[k] * yv.y;
            o.z += w[k] * yv.z; o.w += w[k] * yv.w;
        }
        *(float4*)&out[obase + j * 4] = o;
    }
}

static void* sym(const void* s) { void* p; cudaGetSymbolAddress(&p, s); return p; }

extern "C" void kernel_launch(void* const* d_in, const int* in_sizes, int n_in,
                              void* d_out, int out_size)
{
    (void)in_sizes; (void)n_in; (void)out_size;
    const float* x   = (const float*)d_in[0];
    const float* gw  = (const float*)d_in[1];
    const float* gb  = (const float*)d_in[2];
    const float* w1s = (const float*)d_in[3];
    const float* w2s = (const float*)d_in[4];
    const float* w3s = (const float*)d_in[5];
    const float* w1r = (const float*)d_in[6];
    const float* w2r = (const float*)d_in[7];
    const float* w3r = (const float*)d_in[8];
    float* out = (float*)d_out;

    fp16 *x16 = (fp16*)sym(g_x16);
    fp16 *Gs = (fp16*)sym(g_Gs), *Gr = (fp16*)sym(g_Gr);
    fp16 *Hs = (fp16*)sym(g_Hs), *Hr = (fp16*)sym(g_Hr);
    float *Yr = (float*)sym(g_Yr);

    cudaFuncSetAttribute(gemm_k<true>,  cudaFuncAttributeMaxDynamicSharedMemorySize, GSMEM);
    cudaFuncSetAttribute(gemm_k<false>, cudaFuncAttributeMaxDynamicSharedMemorySize, GSMEM);

    zero_counts_kernel<<<1, 32>>>();
    gate_kernel<<<NT, 256>>>(x, gw, gb);

    {
        int n4 = (int)((size_t)NT * DIM / 4);
        cvtx_kernel<<<n4 / (256 * 8), 256>>>((const float4*)x, (uint2*)x16);
    }

    // up GEMM: y covers 2*HID/128 = 22 tiles (0-10 W1, 11-21 W3); z: 0 shared, 1..16 experts
    gemm_k<true><<<dim3(NT / 256, G_W / 128, NE + 1), 512, GSMEM>>>(
        x16, x16, w1s, w3s, w1r, w3r, Gs, Gr, nullptr, nullptr);

    // activation
    {
        int ns = NT * (HID / 8);
        act_kernel<false><<<(ns + 255) / 256, 256>>>(Gs, Hs, ns);
        int nr = NT * TOPK * (HID / 8);
        act_kernel<true><<<(nr + 255) / 256, 256>>>(Gr, Hr, nr);
    }

    // down GEMM
    gemm_k<false><<<dim3(NT / 256, DIM / 128, NE + 1), 512, GSMEM>>>(
        Hs, Hr, w2s, nullptr, w2r, nullptr, nullptr, nullptr, out, Yr);

    gather_kernel<<<NT, 256>>>(Yr, out);
}

// round 15
// speedup vs baseline: 1.2130x; 1.2130x over previous
#include <cuda_runtime.h>
#include <cuda_fp16.h>
#include <math.h>
#include <stdint.h>

#define NT   2048
#define DIM  2048
#define HID  1408
#define NE   16
#define TOPK 4
#define KC   32

typedef __half fp16;

// ---- routing scratch ----
__device__ int   g_counts[NE];
__device__ int   g_entries[NE * NT];
__device__ float g_slotw[NT * TOPK];

// ---- fp16 activations ----
__device__ fp16  g_x16[NT * DIM];
__device__ fp16  g_Hs[(size_t)NT * HID];
__device__ fp16  g_Hr[(size_t)NT * TOPK * HID];

__device__ __forceinline__ uint32_t h2u(float a, float b) {
    __half2 h = __floats2half2_rn(a, b);
    return *(uint32_t*)&h;
}

// ---- fp32 -> fp16 convert (x); block 0 also zeroes expert counts ----
__global__ __launch_bounds__(256) void cvtx_kernel(const float4* __restrict__ src,
                                                   uint2* __restrict__ dst)
{
    if (blockIdx.x == 0 && threadIdx.x < NE) g_counts[threadIdx.x] = 0;
    int stride = gridDim.x * blockDim.x;
    int i = blockIdx.x * blockDim.x + threadIdx.x;
    float4 v[8];
    #pragma unroll
    for (int j = 0; j < 8; j++) v[j] = __ldcs(src + i + j * stride);
    #pragma unroll
    for (int j = 0; j < 8; j++) {
        uint2 o;
        o.x = h2u(v[j].x, v[j].y);
        o.y = h2u(v[j].z, v[j].w);
        __stcs(dst + i + j * stride, o);
    }
}

// ---------------- gate ----------------
__global__ __launch_bounds__(256) void gate_kernel(const float* __restrict__ x,
                                                   const float* __restrict__ gw,
                                                   const float* __restrict__ gb)
{
    int t = blockIdx.x;
    __shared__ float xs[DIM];
    for (int i = threadIdx.x; i < DIM; i += blockDim.x)
        xs[i] = x[(size_t)t * DIM + i];
    __syncthreads();

    __shared__ float logits[NE];
    int warp = threadIdx.x >> 5, lane = threadIdx.x & 31;
    for (int e = warp; e < NE; e += 8) {
        const float* w = gw + (size_t)e * DIM;
        float s = 0.f;
        for (int d = lane; d < DIM; d += 32) s += w[d] * xs[d];
        #pragma unroll
        for (int o = 16; o > 0; o >>= 1) s += __shfl_down_sync(0xffffffffu, s, o);
        if (lane == 0) logits[e] = s;
    }
    __syncthreads();

    if (threadIdx.x == 0) {
        float sc[NE];
        #pragma unroll
        for (int e = 0; e < NE; e++)
            sc[e] = 1.f / (1.f + expf(-logits[e])) + gb[e];
        int idx[TOPK]; float wv[TOPK]; float sum = 0.f;
        bool used[NE];
        #pragma unroll
        for (int e = 0; e < NE; e++) used[e] = false;
        #pragma unroll
        for (int k = 0; k < TOPK; k++) {
            float best = -1e30f; int bi = 0;
            #pragma unroll
            for (int e = 0; e < NE; e++)
                if (!used[e] && sc[e] > best) { best = sc[e]; bi = e; }
            used[bi] = true; idx[k] = bi; wv[k] = best; sum += best;
        }
        float inv = 1.f / sum;
        #pragma unroll
        for (int k = 0; k < TOPK; k++) {
            int e = idx[k];
            int pos = atomicAdd(&g_counts[e], 1);
            g_entries[e * NT + pos] = t * TOPK + k;
            g_slotw[t * TOPK + k]   = wv[k] * inv;
        }
    }
}

__device__ __forceinline__ float sigmoidf_(float v) { return 1.f / (1.f + expf(-v)); }

// ---------------- asm helpers ----------------
__device__ __forceinline__ uint32_t saddr(const void* p) {
    return (uint32_t)__cvta_generic_to_shared(p);
}
__device__ __forceinline__ void cpa(uint32_t dst, const void* src) {
    asm volatile("cp.async.cg.shared.global [%0], [%1], 16;" :: "r"(dst), "l"(src));
}
__device__ __forceinline__ void cp_commit() { asm volatile("cp.async.commit_group;"); }
__device__ __forceinline__ void cp_wait2()  { asm volatile("cp.async.wait_group 2;"); }
__device__ __forceinline__ void ldsm_x4(uint32_t r[4], uint32_t a) {
    asm volatile("ldmatrix.sync.aligned.m8n8.x4.shared.b16 {%0,%1,%2,%3}, [%4];"
                 : "=r"(r[0]), "=r"(r[1]), "=r"(r[2]), "=r"(r[3]) : "r"(a));
}
__device__ __forceinline__ void ldsm_x4t(uint32_t r[4], uint32_t a) {
    asm volatile("ldmatrix.sync.aligned.m8n8.x4.trans.shared.b16 {%0,%1,%2,%3}, [%4];"
                 : "=r"(r[0]), "=r"(r[1]), "=r"(r[2]), "=r"(r[3]) : "r"(a));
}
__device__ __forceinline__ void mma16816(float c[4], const uint32_t a[4], const uint32_t b[2]) {
    asm volatile("mma.sync.aligned.m16n8k16.row.col.f32.f16.f16.f32 "
                 "{%0,%1,%2,%3}, {%4,%5,%6,%7}, {%8,%9}, {%0,%1,%2,%3};"
                 : "+f"(c[0]), "+f"(c[1]), "+f"(c[2]), "+f"(c[3])
                 : "r"(a[0]), "r"(a[1]), "r"(a[2]), "r"(a[3]), "r"(b[0]), "r"(b[1]));
}

#define APITCH 40
#define BP_UP  72
#define BP_DN  136
#define A_ST   (128 * APITCH)
#define BU_ST  (32 * BP_UP)
#define BD_ST  (32 * BP_DN)
#define UP_STAGE   ((A_ST + 2 * BU_ST) * 2)   // 19456 B
#define DOWN_STAGE ((A_ST + BD_ST) * 2)       // 18944 B
#define UP_SMEM    (4 * UP_STAGE)             // 77.8 KB -> 2 CTAs/SM
#define DOWN_SMEM  (4 * DOWN_STAGE)           // 75.8 KB -> 2 CTAs/SM

// ================ up: merged shared(z=0) + routed(z=1..16) ================
__global__ __launch_bounds__(256, 2) void up_k(
        const fp16* __restrict__ X,
        const float* __restrict__ W1s, const float* __restrict__ W3s,
        const float* __restrict__ W1r, const float* __restrict__ W3r,
        fp16* __restrict__ Os, fp16* __restrict__ Or)
{
    int z = blockIdx.z;
    bool routed = z > 0;
    int e = z - 1;
    int M = routed ? g_counts[e] : NT;
    int m0 = blockIdx.x * 128;
    if (m0 >= M) return;
    int n0 = blockIdx.y * 64;
    const float* w1 = routed ? W1r + (size_t)e * DIM * HID : W1s;
    const float* w3 = routed ? W3r + (size_t)e * DIM * HID : W3s;
    fp16* O = routed ? Or : Os;

    extern __shared__ char smem[];
    int tid = threadIdx.x, lane = tid & 31, warp = tid >> 5;
    int wm = (warp & 3) * 32, wn = (warp >> 2) * 32;

    int ar = tid >> 1, ac = (tid & 1) * 16;
    int gr = m0 + ar; if (gr >= M) gr = m0;
    int tok = routed ? (g_entries[e * NT + gr] >> 2) : gr;
    const fp16* srcA = X + (size_t)tok * DIM + ac;

    int br = tid >> 3, bc = (tid & 7) * 8;
    const float* src1 = w1 + (size_t)br * HID + n0 + bc;
    const float* src3 = w3 + (size_t)br * HID + n0 + bc;

    uint32_t sb = saddr(smem);
    uint32_t offA  = (uint32_t)(ar * APITCH + ac) * 2;
    uint32_t offB1 = (A_ST + br * BP_UP + bc) * 2;
    uint32_t offB3 = offB1 + BU_ST * 2;

    float acc1[2][4][4] = {}, acc3[2][4][4] = {};
    float4 b1v[2], b3v[2];

    auto loadA = [&](int st, int k0) {
        uint32_t base = sb + st * UP_STAGE;
        cpa(base + offA,      srcA + k0);
        cpa(base + offA + 16, srcA + k0 + 8);
    };
    auto ldgB = [&](int k0) {
        const float4* p1 = (const float4*)(src1 + (size_t)k0 * HID);
        const float4* p3 = (const float4*)(src3 + (size_t)k0 * HID);
        b1v[0] = __ldg(p1); b1v[1] = __ldg(p1 + 1);
        b3v[0] = __ldg(p3); b3v[1] = __ldg(p3 + 1);
    };
    auto stsB = [&](int st) {
        char* base = smem + st * UP_STAGE;
        uint4 o1, o3;
        o1.x = h2u(b1v[0].x, b1v[0].y); o1.y = h2u(b1v[0].z, b1v[0].w);
        o1.z = h2u(b1v[1].x, b1v[1].y); o1.w = h2u(b1v[1].z, b1v[1].w);
        o3.x = h2u(b3v[0].x, b3v[0].y); o3.y = h2u(b3v[0].z, b3v[0].w);
        o3.z = h2u(b3v[1].x, b3v[1].y); o3.w = h2u(b3v[1].z, b3v[1].w);
        *(uint4*)(base + offB1) = o1;
        *(uint4*)(base + offB3) = o3;
    };

    // prologue
    ldgB(0);  stsB(0);  ldgB(KC);
    loadA(0, 0);      cp_commit();
    loadA(1, KC);     cp_commit();
    loadA(2, 2 * KC); cp_commit();

    const int KT = DIM / KC;
    for (int t = 0; t < KT; t++) {
        int st = t & 3;
        cp_wait2();
        __syncthreads();   // single barrier per iteration (4-stage ring)
        if (t + 1 < KT) stsB((t + 1) & 3);
        if (t + 2 < KT) ldgB((t + 2) * KC);
        if (t + 3 < KT) loadA((t + 3) & 3, (t + 3) * KC);
        cp_commit();

        uint32_t base = sb + st * UP_STAGE;
        #pragma unroll
        for (int kk = 0; kk < KC; kk += 16) {
            uint32_t ah[2][4];
            #pragma unroll
            for (int mi = 0; mi < 2; mi++) {
                uint32_t ao = ((wm + mi * 16 + (lane & 15)) * APITCH + kk + ((lane >> 4) << 3)) * 2;
                ldsm_x4(ah[mi], base + ao);
            }
            uint32_t b1[2][4], b3[2][4];
            #pragma unroll
            for (int g = 0; g < 2; g++) {
                uint32_t bo = ((kk + (lane & 15)) * BP_UP + wn + g * 16 + ((lane >> 4) << 3)) * 2;
                ldsm_x4t(b1[g], base + A_ST * 2 + bo);
                ldsm_x4t(b3[g], base + (A_ST + BU_ST) * 2 + bo);
            }
            #pragma unroll
            for (int ni = 0; ni < 4; ni++) {
                int g = ni >> 1, o = (ni & 1) * 2;
                #pragma unroll
                for (int mi = 0; mi < 2; mi++) {
                    mma16816(acc1[mi][ni], ah[mi], &b1[g][o]);
                    mma16816(acc3[mi][ni], ah[mi], &b3[g][o]);
                }
            }
        }
    }

    #pragma unroll
    for (int mi = 0; mi < 2; mi++)
        #pragma unroll
        for (int half = 0; half < 2; half++) {
            int r = m0 + wm + mi * 16 + (lane >> 2) + half * 8;
            if (r >= M) continue;
            size_t orow = routed ? (size_t)g_entries[e * NT + r] : (size_t)r;
            #pragma unroll
            for (int ni = 0; ni < 4; ni++) {
                float v1a = acc1[mi][ni][half * 2 + 0], v1b = acc1[mi][ni][half * 2 + 1];
                float v3a = acc3[mi][ni][half * 2 + 0], v3b = acc3[mi][ni][half * 2 + 1];
                float oa, ob;
                if (routed) {
                    float pa = v1a * v3a, pb = v1b * v3b;
                    oa = pa * sigmoidf_(pa);
                    ob = pb * sigmoidf_(pb);
                } else {
                    oa = v1a * sigmoidf_(v1a) * v3a;
                    ob = v1b * sigmoidf_(v1b) * v3b;
                }
                __half2 h2 = __floats2half2_rn(oa, ob);
                *(__half2*)&O[orow * HID + n0 + wn + ni * 8 + ((lane & 3) << 1)] = h2;
            }
        }
}

// ================ down: merged; ALL slices atomicAdd into zeroed out ============
__global__ __launch_bounds__(256, 2) void down_k(
        const fp16* __restrict__ Hs, const fp16* __restrict__ Hr,
        const float* __restrict__ W2s, const float* __restrict__ W2r,
        float* __restrict__ out)
{
    int z = blockIdx.z;
    bool routed = z > 0;
    int e = z - 1;
    int M = routed ? g_counts[e] : NT;
    int m0 = blockIdx.x * 128;
    if (m0 >= M) return;
    int n0 = blockIdx.y * 128;
    const float* w2 = routed ? W2r + (size_t)e * HID * DIM : W2s;
    const fp16* H = routed ? Hr : Hs;

    extern __shared__ char smem[];
    int tid = threadIdx.x, lane = tid & 31, warp = tid >> 5;
    int wm = (warp & 1) * 64, wn = (warp >> 1) * 32;

    int ar = tid >> 1, ac = (tid & 1) * 16;
    int gr = m0 + ar; if (gr >= M) gr = m0;
    size_t rid = routed ? (size_t)g_entries[e * NT + gr] : (size_t)gr;
    const fp16* srcA = H + rid * HID + ac;

    int br = tid >> 3, bc = (tid & 7) * 16;
    const float* srcB = w2 + (size_t)br * DIM + n0 + bc;

    uint32_t sb = saddr(smem);
    uint32_t offA = (uint32_t)(ar * APITCH + ac) * 2;
    uint32_t offB = (A_ST + br * BP_DN + bc) * 2;

    float acc[4][4][4] = {};
    float4 bv[4];

    auto loadA = [&](int st, int k0) {
        uint32_t base = sb + st * DOWN_STAGE;
        cpa(base + offA,      srcA + k0);
        cpa(base + offA + 16, srcA + k0 + 8);
    };
    auto ldgB = [&](int k0) {
        const float4* p = (const float4*)(srcB + (size_t)k0 * DIM);
        bv[0] = __ldg(p);     bv[1] = __ldg(p + 1);
        bv[2] = __ldg(p + 2); bv[3] = __ldg(p + 3);
    };
    auto stsB = [&](int st) {
        char* base = smem + st * DOWN_STAGE;
        uint4 o0, o1;
        o0.x = h2u(bv[0].x, bv[0].y); o0.y = h2u(bv[0].z, bv[0].w);
        o0.z = h2u(bv[1].x, bv[1].y); o0.w = h2u(bv[1].z, bv[1].w);
        o1.x = h2u(bv[2].x, bv[2].y); o1.y = h2u(bv[2].z, bv[2].w);
        o1.z = h2u(bv[3].x, bv[3].y); o1.w = h2u(bv[3].z, bv[3].w);
        *(uint4*)(base + offB)      = o0;
        *(uint4*)(base + offB + 16) = o1;
    };

    // prologue
    ldgB(0);  stsB(0);  ldgB(KC);
    loadA(0, 0);      cp_commit();
    loadA(1, KC);     cp_commit();
    loadA(2, 2 * KC); cp_commit();

    const int KT = HID / KC;
    for (int t = 0; t < KT; t++) {
        int st = t & 3;
        cp_wait2();
        __syncthreads();
        if (t + 1 < KT) stsB((t + 1) & 3);
        if (t + 2 < KT) ldgB((t + 2) * KC);
        if (t + 3 < KT) loadA((t + 3) & 3, (t + 3) * KC);
        cp_commit();

        uint32_t base = sb + st * DOWN_STAGE;
        #pragma unroll
        for (int kk = 0; kk < KC; kk += 16) {
            uint32_t ah[4][4];
            #pragma unroll
            for (int mi = 0; mi < 4; mi++) {
                uint32_t ao = ((wm + mi * 16 + (lane & 15)) * APITCH + kk + ((lane >> 4) << 3)) * 2;
                ldsm_x4(ah[mi], base + ao);
            }
            uint32_t bh[2][4];
            #pragma unroll
            for (int g = 0; g < 2; g++) {
                uint32_t bo = ((kk + (lane & 15)) * BP_DN + wn + g * 16 + ((lane >> 4) << 3)) * 2;
                ldsm_x4t(bh[g], base + A_ST * 2 + bo);
            }
            #pragma unroll
            for (int ni = 0; ni < 4; ni++) {
                int g = ni >> 1, o = (ni & 1) * 2;
                #pragma unroll
                for (int mi = 0; mi < 4; mi++)
                    mma16816(acc[mi][ni], ah[mi], &bh[g][o]);
            }
        }
    }

    #pragma unroll
    for (int mi = 0; mi < 4; mi++)
        #pragma unroll
        for (int half = 0; half < 2; half++) {
            int r = m0 + wm + mi * 16 + (lane >> 2) + half * 8;
            if (r >= M) continue;
            int tok; float wgt;
            if (routed) {
                int slot = g_entries[e * NT + r];
                tok = slot >> 2;
                wgt = g_slotw[slot];
            } else { tok = r; wgt = 1.f; }
            size_t obase = (size_t)tok * DIM + n0 + wn;
            #pragma unroll
            for (int ni = 0; ni < 4; ni++) {
                int col = ni * 8 + ((lane & 3) << 1);
                atomicAdd(&out[obase + col],     acc[mi][ni][half * 2 + 0] * wgt);
                atomicAdd(&out[obase + col + 1], acc[mi][ni][half * 2 + 1] * wgt);
            }
        }
}

static void* sym(const void* s) { void* p; cudaGetSymbolAddress(&p, s); return p; }

extern "C" void kernel_launch(void* const* d_in, const int* in_sizes, int n_in,
                              void* d_out, int out_size)
{
    (void)in_sizes; (void)n_in;
    const float* x   = (const float*)d_in[0];
    const float* gw  = (const float*)d_in[1];
    const float* gb  = (const float*)d_in[2];
    const float* w1s = (const float*)d_in[3];
    const float* w2s = (const float*)d_in[4];
    const float* w3s = (const float*)d_in[5];
    const float* w1r = (const float*)d_in[6];
    const float* w2r = (const float*)d_in[7];
    const float* w3r = (const float*)d_in[8];
    float* out = (float*)d_out;

    fp16 *x16 = (fp16*)sym(g_x16);
    fp16 *Hs = (fp16*)sym(g_Hs), *Hr = (fp16*)sym(g_Hr);

    cudaFuncSetAttribute(up_k,   cudaFuncAttributeMaxDynamicSharedMemorySize, UP_SMEM);
    cudaFuncSetAttribute(down_k, cudaFuncAttributeMaxDynamicSharedMemorySize, DOWN_SMEM);

    cudaMemsetAsync(out, 0, (size_t)out_size * sizeof(float));

    {
        int n4 = (int)((size_t)NT * DIM / 4);
        cvtx_kernel<<<n4 / (256 * 8), 256>>>((const float4*)x, (uint2*)x16);  // also zeroes counts
    }
    gate_kernel<<<NT, 256>>>(x, gw, gb);

    // merged up (z=0 shared, z=1..16 routed experts)
    up_k<<<dim3(NT / 128, HID / 64, NE + 1), 256, UP_SMEM>>>(
        x16, w1s, w3s, w1r, w3r, Hs, Hr);
    // merged down: everyone accumulates into zeroed out
    down_k<<<dim3(NT / 128, DIM / 128, NE + 1), 256, DOWN_SMEM>>>(
        Hs, Hr, w2s, w2r, out);
}

// round 16
// speedup vs baseline: 1.2393x; 1.0217x over previous
#include <cuda_runtime.h>
#include <cuda_fp16.h>
#include <math.h>
#include <stdint.h>

#define NT   2048
#define DIM  2048
#define HID  1408
#define NE   16
#define TOPK 4
#define KC   32

typedef __half fp16;

// ---- routing scratch ----
__device__ int   g_counts[NE];
__device__ int   g_entries[NE * NT];
__device__ float g_slotw[NT * TOPK];

// ---- staging ----
__device__ fp16  g_x16[NT * DIM];
__device__ fp16  g_Hs[(size_t)NT * HID];
__device__ fp16  g_Hr[(size_t)NT * TOPK * HID];
__device__ float g_Yr[(size_t)NT * TOPK * DIM];

__device__ __forceinline__ uint32_t h2u(float a, float b) {
    __half2 h = __floats2half2_rn(a, b);
    return *(uint32_t*)&h;
}

__device__ __forceinline__ float sigmoidf_(float v) { return 1.f / (1.f + expf(-v)); }

// ---------------- gate + x convert fused ----------------
// One block per token: loads x row, writes fp16 copy, computes gate top-4.
__global__ __launch_bounds__(256) void gate_cvt_kernel(const float* __restrict__ x,
                                                       const float* __restrict__ gw,
                                                       const float* __restrict__ gb,
                                                       fp16* __restrict__ x16)
{
    int t = blockIdx.x;
    if (t == 0 && threadIdx.x < NE) g_counts[threadIdx.x] = 0;

    __shared__ float xs[DIM];
    // load row (float4) + emit fp16 row
    const float4* src = (const float4*)(x + (size_t)t * DIM);
    uint2* dst = (uint2*)(x16 + (size_t)t * DIM);
    for (int i = threadIdx.x; i < DIM / 4; i += blockDim.x) {
        float4 v = src[i];
        xs[i * 4 + 0] = v.x; xs[i * 4 + 1] = v.y;
        xs[i * 4 + 2] = v.z; xs[i * 4 + 3] = v.w;
        uint2 o;
        o.x = h2u(v.x, v.y);
        o.y = h2u(v.z, v.w);
        dst[i] = o;
    }
    __syncthreads();

    __shared__ float logits[NE];
    int warp = threadIdx.x >> 5, lane = threadIdx.x & 31;
    for (int e = warp; e < NE; e += 8) {
        const float* w = gw + (size_t)e * DIM;
        float s = 0.f;
        for (int d = lane; d < DIM; d += 32) s += w[d] * xs[d];
        #pragma unroll
        for (int o = 16; o > 0; o >>= 1) s += __shfl_down_sync(0xffffffffu, s, o);
        if (lane == 0) logits[e] = s;
    }
    __syncthreads();

    if (threadIdx.x == 0) {
        float sc[NE];
        #pragma unroll
        for (int e = 0; e < NE; e++)
            sc[e] = 1.f / (1.f + expf(-logits[e])) + gb[e];
        int idx[TOPK]; float wv[TOPK]; float sum = 0.f;
        bool used[NE];
        #pragma unroll
        for (int e = 0; e < NE; e++) used[e] = false;
        #pragma unroll
        for (int k = 0; k < TOPK; k++) {
            float best = -1e30f; int bi = 0;
            #pragma unroll
            for (int e = 0; e < NE; e++)
                if (!used[e] && sc[e] > best) { best = sc[e]; bi = e; }
            used[bi] = true; idx[k] = bi; wv[k] = best; sum += best;
        }
        float inv = 1.f / sum;
        #pragma unroll
        for (int k = 0; k < TOPK; k++) {
            int e = idx[k];
            int pos = atomicAdd(&g_counts[e], 1);
            g_entries[e * NT + pos] = t * TOPK + k;
            g_slotw[t * TOPK + k]   = wv[k] * inv;
        }
    }
}

// ---------------- asm helpers ----------------
__device__ __forceinline__ uint32_t saddr(const void* p) {
    return (uint32_t)__cvta_generic_to_shared(p);
}
__device__ __forceinline__ void cpa(uint32_t dst, const void* src) {
    asm volatile("cp.async.cg.shared.global [%0], [%1], 16;" :: "r"(dst), "l"(src));
}
__device__ __forceinline__ void cp_commit() { asm volatile("cp.async.commit_group;"); }
__device__ __forceinline__ void cp_wait2()  { asm volatile("cp.async.wait_group 2;"); }
__device__ __forceinline__ void ldsm_x4(uint32_t r[4], uint32_t a) {
    asm volatile("ldmatrix.sync.aligned.m8n8.x4.shared.b16 {%0,%1,%2,%3}, [%4];"
                 : "=r"(r[0]), "=r"(r[1]), "=r"(r[2]), "=r"(r[3]) : "r"(a));
}
__device__ __forceinline__ void ldsm_x4t(uint32_t r[4], uint32_t a) {
    asm volatile("ldmatrix.sync.aligned.m8n8.x4.trans.shared.b16 {%0,%1,%2,%3}, [%4];"
                 : "=r"(r[0]), "=r"(r[1]), "=r"(r[2]), "=r"(r[3]) : "r"(a));
}
__device__ __forceinline__ void mma16816(float c[4], const uint32_t a[4], const uint32_t b[2]) {
    asm volatile("mma.sync.aligned.m16n8k16.row.col.f32.f16.f16.f32 "
                 "{%0,%1,%2,%3}, {%4,%5,%6,%7}, {%8,%9}, {%0,%1,%2,%3};"
                 : "+f"(c[0]), "+f"(c[1]), "+f"(c[2]), "+f"(c[3])
                 : "r"(a[0]), "r"(a[1]), "r"(a[2]), "r"(a[3]), "r"(b[0]), "r"(b[1]));
}

#define APITCH 40
#define BP_UP  72
#define BP_DN  136
#define A_ST   (128 * APITCH)
#define BU_ST  (32 * BP_UP)
#define BD_ST  (32 * BP_DN)
#define UP_STAGE   ((A_ST + 2 * BU_ST) * 2)   // 19456 B
#define DOWN_STAGE ((A_ST + BD_ST) * 2)       // 18944 B
#define UP_SMEM    (4 * UP_STAGE)             // 77.8 KB -> 2 CTAs/SM
#define DOWN_SMEM  (4 * DOWN_STAGE)           // 75.8 KB -> 2 CTAs/SM

// ================ up: merged shared(z=0) + routed(z=1..16) ================
__global__ __launch_bounds__(256, 2) void up_k(
        const fp16* __restrict__ X,
        const float* __restrict__ W1s, const float* __restrict__ W3s,
        const float* __restrict__ W1r, const float* __restrict__ W3r,
        fp16* __restrict__ Os, fp16* __restrict__ Or)
{
    int z = blockIdx.z;
    bool routed = z > 0;
    int e = z - 1;
    int M = routed ? g_counts[e] : NT;
    int m0 = blockIdx.x * 128;
    if (m0 >= M) return;
    int n0 = blockIdx.y * 64;
    const float* w1 = routed ? W1r + (size_t)e * DIM * HID : W1s;
    const float* w3 = routed ? W3r + (size_t)e * DIM * HID : W3s;
    fp16* O = routed ? Or : Os;

    extern __shared__ char smem[];
    int tid = threadIdx.x, lane = tid & 31, warp = tid >> 5;
    int wm = (warp & 3) * 32, wn = (warp >> 2) * 32;

    int ar = tid >> 1, ac = (tid & 1) * 16;
    int gr = m0 + ar; if (gr >= M) gr = m0;
    int tok = routed ? (g_entries[e * NT + gr] >> 2) : gr;
    const fp16* srcA = X + (size_t)tok * DIM + ac;

    int br = tid >> 3, bc = (tid & 7) * 8;
    const float* src1 = w1 + (size_t)br * HID + n0 + bc;
    const float* src3 = w3 + (size_t)br * HID + n0 + bc;

    uint32_t sb = saddr(smem);
    uint32_t offA  = (uint32_t)(ar * APITCH + ac) * 2;
    uint32_t offB1 = (A_ST + br * BP_UP + bc) * 2;
    uint32_t offB3 = offB1 + BU_ST * 2;

    float acc1[2][4][4] = {}, acc3[2][4][4] = {};
    float4 b1v[2], b3v[2];

    auto loadA = [&](int st, int k0) {
        uint32_t base = sb + st * UP_STAGE;
        cpa(base + offA,      srcA + k0);
        cpa(base + offA + 16, srcA + k0 + 8);
    };
    auto ldgB = [&](int k0) {
        const float4* p1 = (const float4*)(src1 + (size_t)k0 * HID);
        const float4* p3 = (const float4*)(src3 + (size_t)k0 * HID);
        b1v[0] = __ldg(p1); b1v[1] = __ldg(p1 + 1);
        b3v[0] = __ldg(p3); b3v[1] = __ldg(p3 + 1);
    };
    auto stsB = [&](int st) {
        char* base = smem + st * UP_STAGE;
        uint4 o1, o3;
        o1.x = h2u(b1v[0].x, b1v[0].y); o1.y = h2u(b1v[0].z, b1v[0].w);
        o1.z = h2u(b1v[1].x, b1v[1].y); o1.w = h2u(b1v[1].z, b1v[1].w);
        o3.x = h2u(b3v[0].x, b3v[0].y); o3.y = h2u(b3v[0].z, b3v[0].w);
        o3.z = h2u(b3v[1].x, b3v[1].y); o3.w = h2u(b3v[1].z, b3v[1].w);
        *(uint4*)(base + offB1) = o1;
        *(uint4*)(base + offB3) = o3;
    };

    // prologue
    ldgB(0);  stsB(0);  ldgB(KC);
    loadA(0, 0);      cp_commit();
    loadA(1, KC);     cp_commit();
    loadA(2, 2 * KC); cp_commit();

    const int KT = DIM / KC;
    for (int t = 0; t < KT; t++) {
        int st = t & 3;
        cp_wait2();
        __syncthreads();   // single barrier per iteration (4-stage ring)
        if (t + 1 < KT) stsB((t + 1) & 3);
        if (t + 2 < KT) ldgB((t + 2) * KC);
        if (t + 3 < KT) loadA((t + 3) & 3, (t + 3) * KC);
        cp_commit();

        uint32_t base = sb + st * UP_STAGE;
        #pragma unroll
        for (int kk = 0; kk < KC; kk += 16) {
            uint32_t ah[2][4];
            #pragma unroll
            for (int mi = 0; mi < 2; mi++) {
                uint32_t ao = ((wm + mi * 16 + (lane & 15)) * APITCH + kk + ((lane >> 4) << 3)) * 2;
                ldsm_x4(ah[mi], base + ao);
            }
            uint32_t b1[2][4], b3[2][4];
            #pragma unroll
            for (int g = 0; g < 2; g++) {
                uint32_t bo = ((kk + (lane & 15)) * BP_UP + wn + g * 16 + ((lane >> 4) << 3)) * 2;
                ldsm_x4t(b1[g], base + A_ST * 2 + bo);
                ldsm_x4t(b3[g], base + (A_ST + BU_ST) * 2 + bo);
            }
            #pragma unroll
            for (int ni = 0; ni < 4; ni++) {
                int g = ni >> 1, o = (ni & 1) * 2;
                #pragma unroll
                for (int mi = 0; mi < 2; mi++) {
                    mma16816(acc1[mi][ni], ah[mi], &b1[g][o]);
                    mma16816(acc3[mi][ni], ah[mi], &b3[g][o]);
                }
            }
        }
    }

    #pragma unroll
    for (int mi = 0; mi < 2; mi++)
        #pragma unroll
        for (int half = 0; half < 2; half++) {
            int r = m0 + wm + mi * 16 + (lane >> 2) + half * 8;
            if (r >= M) continue;
            size_t orow = routed ? (size_t)g_entries[e * NT + r] : (size_t)r;
            #pragma unroll
            for (int ni = 0; ni < 4; ni++) {
                float v1a = acc1[mi][ni][half * 2 + 0], v1b = acc1[mi][ni][half * 2 + 1];
                float v3a = acc3[mi][ni][half * 2 + 0], v3b = acc3[mi][ni][half * 2 + 1];
                float oa, ob;
                if (routed) {
                    float pa = v1a * v3a, pb = v1b * v3b;
                    oa = pa * sigmoidf_(pa);
                    ob = pb * sigmoidf_(pb);
                } else {
                    oa = v1a * sigmoidf_(v1a) * v3a;
                    ob = v1b * sigmoidf_(v1b) * v3b;
                }
                __half2 h2 = __floats2half2_rn(oa, ob);
                *(__half2*)&O[orow * HID + n0 + wn + ni * 8 + ((lane & 3) << 1)] = h2;
            }
        }
}

// ================ down: merged shared(z=0, ->out) + routed(z>0, ->Yr) ============
__global__ __launch_bounds__(256, 2) void down_k(
        const fp16* __restrict__ Hs, const fp16* __restrict__ Hr,
        const float* __restrict__ W2s, const float* __restrict__ W2r,
        float* __restrict__ outp, float* __restrict__ Yr)
{
    int z = blockIdx.z;
    bool routed = z > 0;
    int e = z - 1;
    int M = routed ? g_counts[e] : NT;
    int m0 = blockIdx.x * 128;
    if (m0 >= M) return;
    int n0 = blockIdx.y * 128;
    const float* w2 = routed ? W2r + (size_t)e * HID * DIM : W2s;
    const fp16* H = routed ? Hr : Hs;
    float* out = routed ? Yr : outp;

    extern __shared__ char smem[];
    int tid = threadIdx.x, lane = tid & 31, warp = tid >> 5;
    int wm = (warp & 1) * 64, wn = (warp >> 1) * 32;

    int ar = tid >> 1, ac = (tid & 1) * 16;
    int gr = m0 + ar; if (gr >= M) gr = m0;
    size_t rid = routed ? (size_t)g_entries[e * NT + gr] : (size_t)gr;
    const fp16* srcA = H + rid * HID + ac;

    int br = tid >> 3, bc = (tid & 7) * 16;
    const float* srcB = w2 + (size_t)br * DIM + n0 + bc;

    uint32_t sb = saddr(smem);
    uint32_t offA = (uint32_t)(ar * APITCH + ac) * 2;
    uint32_t offB = (A_ST + br * BP_DN + bc) * 2;

    float acc[4][4][4] = {};
    float4 bv[4];

    auto loadA = [&](int st, int k0) {
        uint32_t base = sb + st * DOWN_STAGE;
        cpa(base + offA,      srcA + k0);
        cpa(base + offA + 16, srcA + k0 + 8);
    };
    auto ldgB = [&](int k0) {
        const float4* p = (const float4*)(srcB + (size_t)k0 * DIM);
        bv[0] = __ldg(p);     bv[1] = __ldg(p + 1);
        bv[2] = __ldg(p + 2); bv[3] = __ldg(p + 3);
    };
    auto stsB = [&](int st) {
        char* base = smem + st * DOWN_STAGE;
        uint4 o0, o1;
        o0.x = h2u(bv[0].x, bv[0].y); o0.y = h2u(bv[0].z, bv[0].w);
        o0.z = h2u(bv[1].x, bv[1].y); o0.w = h2u(bv[1].z, bv[1].w);
        o1.x = h2u(bv[2].x, bv[2].y); o1.y = h2u(bv[2].z, bv[2].w);
        o1.z = h2u(bv[3].x, bv[3].y); o1.w = h2u(bv[3].z, bv[3].w);
        *(uint4*)(base + offB)      = o0;
        *(uint4*)(base + offB + 16) = o1;
    };

    // prologue
    ldgB(0);  stsB(0);  ldgB(KC);
    loadA(0, 0);      cp_commit();
    loadA(1, KC);     cp_commit();
    loadA(2, 2 * KC); cp_commit();

    const int KT = HID / KC;
    for (int t = 0; t < KT; t++) {
        int st = t & 3;
        cp_wait2();
        __syncthreads();   // single barrier per iteration
        if (t + 1 < KT) stsB((t + 1) & 3);
        if (t + 2 < KT) ldgB((t + 2) * KC);
        if (t + 3 < KT) loadA((t + 3) & 3, (t + 3) * KC);
        cp_commit();

        uint32_t base = sb + st * DOWN_STAGE;
        #pragma unroll
        for (int kk = 0; kk < KC; kk += 16) {
            uint32_t ah[4][4];
            #pragma unroll
            for (int mi = 0; mi < 4; mi++) {
                uint32_t ao = ((wm + mi * 16 + (lane & 15)) * APITCH + kk + ((lane >> 4) << 3)) * 2;
                ldsm_x4(ah[mi], base + ao);
            }
            uint32_t bh[2][4];
            #pragma unroll
            for (int g = 0; g < 2; g++) {
                uint32_t bo = ((kk + (lane & 15)) * BP_DN + wn + g * 16 + ((lane >> 4) << 3)) * 2;
                ldsm_x4t(bh[g], base + A_ST * 2 + bo);
            }
            #pragma unroll
            for (int ni = 0; ni < 4; ni++) {
                int g = ni >> 1, o = (ni & 1) * 2;
                #pragma unroll
                for (int mi = 0; mi < 4; mi++)
                    mma16816(acc[mi][ni], ah[mi], &bh[g][o]);
            }
        }
    }

    #pragma unroll
    for (int mi = 0; mi < 4; mi++)
        #pragma unroll
        for (int half = 0; half < 2; half++) {
            int r = m0 + wm + mi * 16 + (lane >> 2) + half * 8;
            if (r >= M) continue;
            size_t orow = routed ? (size_t)g_entries[e * NT + r] : (size_t)r;
            #pragma unroll
            for (int ni = 0; ni < 4; ni++) {
                float2 o;
                o.x = acc[mi][ni][half * 2 + 0];
                o.y = acc[mi][ni][half * 2 + 1];
                *(float2*)&out[orow * DIM + n0 + wn + ni * 8 + ((lane & 3) << 1)] = o;
            }
        }
}

// ---- gather: out[t] += sum_k w[4t+k] * Yr[4t+k] ----
__global__ __launch_bounds__(256) void gather_kernel(const float* __restrict__ Yr,
                                                     float* __restrict__ out)
{
    int t = blockIdx.x;
    int d0 = threadIdx.x * 8;
    float w[TOPK];
    #pragma unroll
    for (int k = 0; k < TOPK; k++) w[k] = g_slotw[t * TOPK + k];
    size_t obase = (size_t)t * DIM + d0;
    #pragma unroll
    for (int j = 0; j < 2; j++) {
        float4 o = *(const float4*)&out[obase + j * 4];
        #pragma unroll
        for (int k = 0; k < TOPK; k++) {
            float4 y = __ldcs((const float4*)&Yr[((size_t)t * TOPK + k) * DIM + d0 + j * 4]);
            o.x += w[k] * y.x; o.y += w[k] * y.y;
            o.z += w[k] * y.z; o.w += w[k] * y.w;
        }
        *(float4*)&out[obase + j * 4] = o;
    }
}

static void* sym(const void* s) { void* p; cudaGetSymbolAddress(&p, s); return p; }

extern "C" void kernel_launch(void* const* d_in, const int* in_sizes, int n_in,
                              void* d_out, int out_size)
{
    (void)in_sizes; (void)n_in; (void)out_size;
    const float* x   = (const float*)d_in[0];
    const float* gw  = (const float*)d_in[1];
    const float* gb  = (const float*)d_in[2];
    const float* w1s = (const float*)d_in[3];
    const float* w2s = (const float*)d_in[4];
    const float* w3s = (const float*)d_in[5];
    const float* w1r = (const float*)d_in[6];
    const float* w2r = (const float*)d_in[7];
    const float* w3r = (const float*)d_in[8];
    float* out = (float*)d_out;

    fp16 *x16 = (fp16*)sym(g_x16);
    fp16 *Hs = (fp16*)sym(g_Hs), *Hr = (fp16*)sym(g_Hr);
    float *Yr = (float*)sym(g_Yr);

    cudaFuncSetAttribute(up_k,   cudaFuncAttributeMaxDynamicSharedMemorySize, UP_SMEM);
    cudaFuncSetAttribute(down_k, cudaFuncAttributeMaxDynamicSharedMemorySize, DOWN_SMEM);

    // fused: zero counts + gate + x->fp16 convert
    gate_cvt_kernel<<<NT, 256>>>(x, gw, gb, x16);

    // merged up (z=0 shared, z=1..16 routed experts)
    up_k<<<dim3(NT / 128, HID / 64, NE + 1), 256, UP_SMEM>>>(
        x16, w1s, w3s, w1r, w3r, Hs, Hr);
    // merged down
    down_k<<<dim3(NT / 128, DIM / 128, NE + 1), 256, DOWN_SMEM>>>(
        Hs, Hr, w2s, w2r, out, Yr);
    gather_kernel<<<NT, 256>>>(Yr, out);
}